// round 1
// baseline (speedup 1.0000x reference)
#include <cuda_runtime.h>
#include <math.h>

#define S_LEN 2048
#define HID   4096
#define NH    32
#define NKV   8
#define HD    128
#define KVDIM (NKV * HD)   // 1024

// Scratch (device-global; no allocation allowed)
__device__ float g_Q[(size_t)S_LEN * HID];    // [s][h][d]  32 MB
__device__ float g_K[(size_t)S_LEN * KVDIM];  // [s][kvh][d] 8 MB
__device__ float g_V[(size_t)S_LEN * KVDIM];  //             8 MB
__device__ float g_A[(size_t)S_LEN * HID];    // attn out   32 MB

// ---------------------------------------------------------------------------
// GEMM: C[M,N] = A[M,K] * B[N,K]^T   (all row-major, dims multiples of 128/16)
// 128x128 tile, BK=16, 256 threads, 8x8 per thread.
// ---------------------------------------------------------------------------
__global__ __launch_bounds__(256) void gemm_nt(const float* __restrict__ A,
                                               const float* __restrict__ B,
                                               float* __restrict__ C,
                                               int M, int N, int K)
{
    __shared__ float As[16][128];
    __shared__ float Bs[16][128];

    const int tid = threadIdx.x;
    const int tx = tid & 15;         // 0..15 -> N direction
    const int ty = tid >> 4;         // 0..15 -> M direction
    const int m0 = blockIdx.y * 128;
    const int n0 = blockIdx.x * 128;

    const float* Ap = A + (size_t)m0 * K;
    const float* Bp = B + (size_t)n0 * K;

    float acc[8][8];
#pragma unroll
    for (int i = 0; i < 8; i++)
#pragma unroll
        for (int j = 0; j < 8; j++) acc[i][j] = 0.f;

    for (int k0 = 0; k0 < K; k0 += 16) {
        // load A tile (transposed into As[k][m]) and B tile (Bs[k][n])
#pragma unroll
        for (int t = 0; t < 2; t++) {
            int idx = tid + t * 256;        // 0..511
            int row = idx >> 2;             // 0..127
            int kc  = (idx & 3) << 2;       // 0,4,8,12
            float4 va = *(const float4*)&Ap[(size_t)row * K + k0 + kc];
            As[kc + 0][row] = va.x;
            As[kc + 1][row] = va.y;
            As[kc + 2][row] = va.z;
            As[kc + 3][row] = va.w;
            float4 vb = *(const float4*)&Bp[(size_t)row * K + k0 + kc];
            Bs[kc + 0][row] = vb.x;
            Bs[kc + 1][row] = vb.y;
            Bs[kc + 2][row] = vb.z;
            Bs[kc + 3][row] = vb.w;
        }
        __syncthreads();

#pragma unroll
        for (int k = 0; k < 16; k++) {
            float a[8], b[8];
            *(float4*)&a[0] = *(const float4*)&As[k][ty * 8];
            *(float4*)&a[4] = *(const float4*)&As[k][ty * 8 + 4];
            *(float4*)&b[0] = *(const float4*)&Bs[k][tx * 8];
            *(float4*)&b[4] = *(const float4*)&Bs[k][tx * 8 + 4];
#pragma unroll
            for (int i = 0; i < 8; i++)
#pragma unroll
                for (int j = 0; j < 8; j++)
                    acc[i][j] = fmaf(a[i], b[j], acc[i][j]);
        }
        __syncthreads();
    }

#pragma unroll
    for (int i = 0; i < 8; i++) {
        float* c = C + (size_t)(m0 + ty * 8 + i) * N + n0 + tx * 8;
        float4 v0 = make_float4(acc[i][0], acc[i][1], acc[i][2], acc[i][3]);
        float4 v1 = make_float4(acc[i][4], acc[i][5], acc[i][6], acc[i][7]);
        *(float4*)c       = v0;
        *(float4*)(c + 4) = v1;
    }
}

// ---------------------------------------------------------------------------
// RoPE in-place on g_Q (32 heads) and g_K (8 heads).
// grid (S, NH+NKV), block 64. Thread i handles dims (i, i+64).
// ---------------------------------------------------------------------------
__global__ __launch_bounds__(64) void rope_kernel()
{
    const int s = blockIdx.x;
    const int h = blockIdx.y;
    const int i = threadIdx.x;   // 0..63

    float* p;
    if (h < NH) p = &g_Q[(size_t)s * HID + h * HD];
    else        p = &g_K[(size_t)s * KVDIM + (h - NH) * HD];

    float freq = __powf(10000.0f, -((float)(2 * i)) / 128.0f);
    float ang  = (float)s * freq;
    float sn, c;
    sincosf(ang, &sn, &c);

    float x1 = p[i];
    float x2 = p[i + 64];
    p[i]      = x1 * c - x2 * sn;
    p[i + 64] = x2 * c + x1 * sn;
}

// ---------------------------------------------------------------------------
// Flash attention (causal, GQA 4:1). One block = (64-row q tile, head).
// 256 threads. Dynamic smem: Qs[64][128] + Ks[64][128] + Ss[64][64] + stats.
// ---------------------------------------------------------------------------
__global__ __launch_bounds__(256) void flash_attn()
{
    extern __shared__ float sm[];
    float* Qs   = sm;                      // 64*128
    float* Ks   = Qs + 64 * 128;           // 64*128 (reused for V)
    float* Ss   = Ks + 64 * 128;           // 64*64
    float* mrow = Ss + 64 * 64;            // 64
    float* lrow = mrow + 64;               // 64
    float* fac  = lrow + 64;               // 64

    const int qt  = blockIdx.x;            // 0..31
    const int h   = blockIdx.y;            // 0..31
    const int kvh = h >> 2;
    const int tid = threadIdx.x;
    const int tx  = tid & 15;
    const int ty  = tid >> 4;

    // Load Q tile: rows qt*64..+63, head h
#pragma unroll
    for (int t = 0; t < 8; t++) {
        int idx = tid + t * 256;           // 0..2047 (float4 index)
        int row = idx >> 5;                // 0..63
        int d4  = (idx & 31) << 2;         // 0..124
        *(float4*)&Qs[row * 128 + d4] =
            *(const float4*)&g_Q[(size_t)(qt * 64 + row) * HID + h * HD + d4];
    }
    if (tid < 64) { mrow[tid] = -INFINITY; lrow[tid] = 0.f; }

    float o[4][8];
#pragma unroll
    for (int i = 0; i < 4; i++)
#pragma unroll
        for (int j = 0; j < 8; j++) o[i][j] = 0.f;

    __syncthreads();

    const float scale = 0.08838834764831845f;  // 128^-0.5

    for (int jt = 0; jt <= qt; jt++) {
        // load K tile
#pragma unroll
        for (int t = 0; t < 8; t++) {
            int idx = tid + t * 256;
            int row = idx >> 5;
            int d4  = (idx & 31) << 2;
            *(float4*)&Ks[row * 128 + d4] =
                *(const float4*)&g_K[(size_t)(jt * 64 + row) * KVDIM + kvh * HD + d4];
        }
        __syncthreads();

        // scores: thread (ty,tx) computes rows 4ty..+3 x cols 4tx..+3
        float s4[4][4];
#pragma unroll
        for (int i = 0; i < 4; i++)
#pragma unroll
            for (int j = 0; j < 4; j++) s4[i][j] = 0.f;

        for (int d = 0; d < 128; d += 4) {
            float4 qv[4], kv[4];
#pragma unroll
            for (int i = 0; i < 4; i++)
                qv[i] = *(const float4*)&Qs[(ty * 4 + i) * 128 + d];
#pragma unroll
            for (int j = 0; j < 4; j++)
                kv[j] = *(const float4*)&Ks[(tx * 4 + j) * 128 + d];
#pragma unroll
            for (int i = 0; i < 4; i++)
#pragma unroll
                for (int j = 0; j < 4; j++) {
                    s4[i][j] = fmaf(qv[i].x, kv[j].x, s4[i][j]);
                    s4[i][j] = fmaf(qv[i].y, kv[j].y, s4[i][j]);
                    s4[i][j] = fmaf(qv[i].z, kv[j].z, s4[i][j]);
                    s4[i][j] = fmaf(qv[i].w, kv[j].w, s4[i][j]);
                }
        }

#pragma unroll
        for (int i = 0; i < 4; i++)
#pragma unroll
            for (int j = 0; j < 4; j++) {
                float v = s4[i][j] * scale;
                int rg = qt * 64 + ty * 4 + i;
                int cg = jt * 64 + tx * 4 + j;
                if (cg > rg) v = -INFINITY;
                Ss[(ty * 4 + i) * 64 + tx * 4 + j] = v;
            }
        __syncthreads();

        // online softmax per row (threads 0..63)
        if (tid < 64) {
            int r = tid;
            float mo = mrow[r];
            float mx = mo;
#pragma unroll 8
            for (int c = 0; c < 64; c++) mx = fmaxf(mx, Ss[r * 64 + c]);
            float sum = 0.f;
#pragma unroll 8
            for (int c = 0; c < 64; c++) {
                float e = __expf(Ss[r * 64 + c] - mx);
                Ss[r * 64 + c] = e;
                sum += e;
            }
            float f = (mo == -INFINITY) ? 0.f : __expf(mo - mx);
            lrow[r] = lrow[r] * f + sum;
            mrow[r] = mx;
            fac[r]  = f;
        }
        __syncthreads();

        // load V tile (overwrites Ks) + rescale O accumulator
#pragma unroll
        for (int t = 0; t < 8; t++) {
            int idx = tid + t * 256;
            int row = idx >> 5;
            int d4  = (idx & 31) << 2;
            *(float4*)&Ks[row * 128 + d4] =
                *(const float4*)&g_V[(size_t)(jt * 64 + row) * KVDIM + kvh * HD + d4];
        }
#pragma unroll
        for (int i = 0; i < 4; i++) {
            float f = fac[ty * 4 + i];
#pragma unroll
            for (int j = 0; j < 8; j++) o[i][j] *= f;
        }
        __syncthreads();

        // O += P @ V : thread owns rows 4ty..+3, dims 8tx..+7
        for (int kk = 0; kk < 64; kk += 4) {
            float4 p4[4];
#pragma unroll
            for (int i = 0; i < 4; i++)
                p4[i] = *(const float4*)&Ss[(ty * 4 + i) * 64 + kk];
#pragma unroll
            for (int u = 0; u < 4; u++) {
                float4 v0 = *(const float4*)&Ks[(kk + u) * 128 + tx * 8];
                float4 v1 = *(const float4*)&Ks[(kk + u) * 128 + tx * 8 + 4];
#pragma unroll
                for (int i = 0; i < 4; i++) {
                    float p = (u == 0) ? p4[i].x : (u == 1) ? p4[i].y
                             : (u == 2) ? p4[i].z : p4[i].w;
                    o[i][0] = fmaf(p, v0.x, o[i][0]);
                    o[i][1] = fmaf(p, v0.y, o[i][1]);
                    o[i][2] = fmaf(p, v0.z, o[i][2]);
                    o[i][3] = fmaf(p, v0.w, o[i][3]);
                    o[i][4] = fmaf(p, v1.x, o[i][4]);
                    o[i][5] = fmaf(p, v1.y, o[i][5]);
                    o[i][6] = fmaf(p, v1.z, o[i][6]);
                    o[i][7] = fmaf(p, v1.w, o[i][7]);
                }
            }
        }
        __syncthreads();
    }

    // normalize + store: g_A[s][h][d]
#pragma unroll
    for (int i = 0; i < 4; i++) {
        float inv = 1.f / lrow[ty * 4 + i];
        float* dst = &g_A[(size_t)(qt * 64 + ty * 4 + i) * HID + h * HD + tx * 8];
        float4 v0 = make_float4(o[i][0] * inv, o[i][1] * inv, o[i][2] * inv, o[i][3] * inv);
        float4 v1 = make_float4(o[i][4] * inv, o[i][5] * inv, o[i][6] * inv, o[i][7] * inv);
        *(float4*)dst       = v0;
        *(float4*)(dst + 4) = v1;
    }
}

// ---------------------------------------------------------------------------
extern "C" void kernel_launch(void* const* d_in, const int* in_sizes, int n_in,
                              void* d_out, int out_size)
{
    const float* X  = (const float*)d_in[0];   // [2048, 4096]
    const float* Wq = (const float*)d_in[1];   // [4096, 4096]
    const float* Wk = (const float*)d_in[2];   // [1024, 4096]
    const float* Wv = (const float*)d_in[3];   // [1024, 4096]
    const float* Wo = (const float*)d_in[4];   // [4096, 4096]
    float* out = (float*)d_out;                // [2048, 4096]

    float *Qp, *Kp, *Vp, *Ap;
    cudaGetSymbolAddress((void**)&Qp, g_Q);
    cudaGetSymbolAddress((void**)&Kp, g_K);
    cudaGetSymbolAddress((void**)&Vp, g_V);
    cudaGetSymbolAddress((void**)&Ap, g_A);

    // QKV projections
    gemm_nt<<<dim3(HID / 128, S_LEN / 128), 256>>>(X, Wq, Qp, S_LEN, HID, HID);
    gemm_nt<<<dim3(KVDIM / 128, S_LEN / 128), 256>>>(X, Wk, Kp, S_LEN, KVDIM, HID);
    gemm_nt<<<dim3(KVDIM / 128, S_LEN / 128), 256>>>(X, Wv, Vp, S_LEN, KVDIM, HID);

    // RoPE on Q and K
    rope_kernel<<<dim3(S_LEN, NH + NKV), 64>>>();

    // Flash attention
    const int flash_smem = (64 * 128 * 2 + 64 * 64 + 3 * 64) * (int)sizeof(float);
    cudaFuncSetAttribute(flash_attn, cudaFuncAttributeMaxDynamicSharedMemorySize,
                         flash_smem);
    flash_attn<<<dim3(S_LEN / 64, NH), 256, flash_smem>>>();

    // Output projection
    gemm_nt<<<dim3(HID / 128, S_LEN / 128), 256>>>(Ap, Wo, out, S_LEN, HID, HID);
}

// round 4
// speedup vs baseline: 1.2925x; 1.2925x over previous
#include <cuda_runtime.h>
#include <cuda_bf16.h>
#include <cstdint>
#include <math.h>

#define S_LEN 2048
#define HID   4096
#define NH    32
#define NKV   8
#define HD    128
#define KVDIM (NKV * HD)   // 1024

typedef __nv_bfloat16 bf16;

// ------------------------- device scratch (no allocs allowed) --------------
__device__ float g_Q[(size_t)S_LEN * HID];
__device__ float g_K[(size_t)S_LEN * KVDIM];
__device__ float g_V[(size_t)S_LEN * KVDIM];
__device__ float g_A[(size_t)S_LEN * HID];

__device__ bf16 g_Xh[S_LEN * HID],  g_Xl[S_LEN * HID];
__device__ bf16 g_Wqh[HID * HID],   g_Wql[HID * HID];
__device__ bf16 g_Wkh[KVDIM * HID], g_Wkl[KVDIM * HID];
__device__ bf16 g_Wvh[KVDIM * HID], g_Wvl[KVDIM * HID];
__device__ bf16 g_Woh[HID * HID],   g_Wol[HID * HID];
__device__ bf16 g_Ah[S_LEN * HID],  g_Al[S_LEN * HID];

// ------------------------- PTX helpers (sm_80-class only!) ------------------
__device__ __forceinline__ uint32_t smem_u32(const void* p) {
    uint32_t a;
    asm("{ .reg .u64 t; cvta.to.shared.u64 t, %1; cvt.u32.u64 %0, t; }" : "=r"(a) : "l"(p));
    return a;
}
#define CP_ASYNC16(dst, src) \
    asm volatile("cp.async.cg.shared.global [%0], [%1], 16;" :: "r"(dst), "l"(src) : "memory")
#define CP_COMMIT()  asm volatile("cp.async.commit_group;" ::: "memory")
#define CP_WAIT2()   asm volatile("cp.async.wait_group 2;" ::: "memory")

#define LDSM4(r0, r1, r2, r3, addr) \
    asm volatile("ldmatrix.sync.aligned.m8n8.x4.shared.b16 {%0,%1,%2,%3}, [%4];" \
                 : "=r"(r0), "=r"(r1), "=r"(r2), "=r"(r3) : "r"(addr))

__device__ __forceinline__ void mma16816(float* c, const uint32_t* a,
                                         uint32_t b0, uint32_t b1) {
    asm volatile(
        "mma.sync.aligned.m16n8k16.row.col.f32.bf16.bf16.f32 "
        "{%0,%1,%2,%3}, {%4,%5,%6,%7}, {%8,%9}, {%0,%1,%2,%3};"
        : "+f"(c[0]), "+f"(c[1]), "+f"(c[2]), "+f"(c[3])
        : "r"(a[0]), "r"(a[1]), "r"(a[2]), "r"(a[3]), "r"(b0), "r"(b1));
}

// ------------------------- split fp32 -> bf16 hi/lo -------------------------
__global__ __launch_bounds__(256) void split_kernel(const float4* __restrict__ src,
                                                    __nv_bfloat162* __restrict__ hi,
                                                    __nv_bfloat162* __restrict__ lo,
                                                    int n4)
{
    int i = blockIdx.x * 256 + threadIdx.x;
    if (i >= n4) return;
    float4 v = src[i];
    bf16 h0 = __float2bfloat16(v.x), h1 = __float2bfloat16(v.y);
    bf16 h2 = __float2bfloat16(v.z), h3 = __float2bfloat16(v.w);
    bf16 l0 = __float2bfloat16(v.x - __bfloat162float(h0));
    bf16 l1 = __float2bfloat16(v.y - __bfloat162float(h1));
    bf16 l2 = __float2bfloat16(v.z - __bfloat162float(h2));
    bf16 l3 = __float2bfloat16(v.w - __bfloat162float(h3));
    hi[2 * i]     = __halves2bfloat162(h0, h1);
    hi[2 * i + 1] = __halves2bfloat162(h2, h3);
    lo[2 * i]     = __halves2bfloat162(l0, l1);
    lo[2 * i + 1] = __halves2bfloat162(l2, l3);
}

// ------------------------- HMMA GEMM: C = A*B^T (split bf16, 3 passes) ------
// A[M,K], B[N,K] row-major bf16. BM=BN=128, BK=32. 256 threads, 8 warps (4x2).
// Warp tile 32x64 via m16n8k16: 2 m-tiles x 8 n-tiles.
#define BM 128
#define BN 128
#define BKE 32                    // bf16 elems per k-chunk
#define LDS_ROW 80                // bytes per smem row (64 data + 16 pad)
#define A_BYTES (BM * LDS_ROW)    // 10240
#define STAGE   (2 * A_BYTES)     // 20480 (A then B)
#define NSTAGES 4
#define GEMM_SMEM (NSTAGES * STAGE)

__device__ __forceinline__ void issue_loads_mma(int j, int kchunks, int tid,
                                                int m0, int n0, int K,
                                                const bf16* Ah, const bf16* Al,
                                                const bf16* Bh, const bf16* Bl,
                                                uint32_t sbase)
{
    int pass = j / kchunks;
    int k0 = (j - pass * kchunks) * BKE;
    const bf16* Ap = (pass == 1) ? Al : Ah;
    const bf16* Bp = (pass == 2) ? Bl : Bh;
    uint32_t st = sbase + (j & 3) * STAGE;
#pragma unroll
    for (int t = 0; t < 2; t++) {
        int idx = tid + t * 256;          // 0..511
        int row = idx >> 2;               // 0..127
        int ch  = idx & 3;                // 16B chunk
        const bf16* srcA = Ap + (size_t)(m0 + row) * K + k0 + ch * 8;
        CP_ASYNC16(st + row * LDS_ROW + ch * 16, srcA);
    }
#pragma unroll
    for (int t = 0; t < 2; t++) {
        int idx = tid + t * 256;
        int row = idx >> 2;
        int ch  = idx & 3;
        const bf16* srcB = Bp + (size_t)(n0 + row) * K + k0 + ch * 8;
        CP_ASYNC16(st + A_BYTES + row * LDS_ROW + ch * 16, srcB);
    }
}

__global__ __launch_bounds__(256, 1) void gemm_mma(const bf16* __restrict__ Ah,
                                                   const bf16* __restrict__ Al,
                                                   const bf16* __restrict__ Bh,
                                                   const bf16* __restrict__ Bl,
                                                   float* __restrict__ C,
                                                   int M, int N, int K)
{
    extern __shared__ char smem[];
    const uint32_t sbase = smem_u32(smem);
    const int tid  = threadIdx.x;
    const int lane = tid & 31;
    const int wid  = tid >> 5;
    const int wm   = wid & 3;     // 4 warps in M -> 32 rows each
    const int wn   = wid >> 2;    // 2 warps in N -> 64 cols each
    const int m0 = blockIdx.y * BM;
    const int n0 = blockIdx.x * BN;
    const int kchunks = K / BKE;
    const int iters = 3 * kchunks;

    float acc[2][8][4];
#pragma unroll
    for (int i = 0; i < 2; i++)
#pragma unroll
        for (int j = 0; j < 8; j++)
#pragma unroll
            for (int r = 0; r < 4; r++) acc[i][j][r] = 0.f;

    // per-thread ldmatrix address offsets (within a stage)
    // A tile i: row = wm*32 + i*16 + (lane&15), col16 = (lane>>4)*16 bytes
    uint32_t aoff[2];
#pragma unroll
    for (int i = 0; i < 2; i++)
        aoff[i] = (uint32_t)((wm * 32 + i * 16 + (lane & 15)) * LDS_ROW +
                             (lane >> 4) * 16);
    // B pair p: row = wn*64 + p*16 + (lane&7) + ((lane>>4)<<3), col = ((lane>>3)&1)*16
    uint32_t boff[4];
#pragma unroll
    for (int p = 0; p < 4; p++)
        boff[p] = (uint32_t)(A_BYTES +
                             (wn * 64 + p * 16 + (lane & 7) + ((lane >> 4) << 3)) * LDS_ROW +
                             ((lane >> 3) & 1) * 16);

    // prologue: 3 stages in flight
    for (int j = 0; j < 3; j++) {
        issue_loads_mma(j, kchunks, tid, m0, n0, K, Ah, Al, Bh, Bl, sbase);
        CP_COMMIT();
    }

    for (int it = 0; it < iters; it++) {
        uint32_t st = sbase + (it & 3) * STAGE;
        CP_WAIT2();
        __syncthreads();

#pragma unroll
        for (int ks = 0; ks < 2; ks++) {       // two k16 steps per chunk
            uint32_t kb = ks * 32;             // 16 elems * 2B
            uint32_t af[2][4];
#pragma unroll
            for (int i = 0; i < 2; i++)
                LDSM4(af[i][0], af[i][1], af[i][2], af[i][3], st + aoff[i] + kb);
            uint32_t bfr[4][4];
#pragma unroll
            for (int p = 0; p < 4; p++)
                LDSM4(bfr[p][0], bfr[p][1], bfr[p][2], bfr[p][3], st + boff[p] + kb);
#pragma unroll
            for (int i = 0; i < 2; i++)
#pragma unroll
                for (int j = 0; j < 8; j++) {
                    int p = j >> 1;
                    int h = (j & 1) << 1;
                    mma16816(acc[i][j], af[i], bfr[p][h], bfr[p][h + 1]);
                }
        }
        __syncthreads();

        int nj = it + 3;
        if (nj < iters)
            issue_loads_mma(nj, kchunks, tid, m0, n0, K, Ah, Al, Bh, Bl, sbase);
        CP_COMMIT();
    }

    // epilogue
    const int g   = lane >> 2;
    const int tig = lane & 3;
#pragma unroll
    for (int i = 0; i < 2; i++) {
        int row = m0 + wm * 32 + i * 16 + g;
#pragma unroll
        for (int j = 0; j < 8; j++) {
            int col = n0 + wn * 64 + j * 8 + 2 * tig;
            *(float2*)&C[(size_t)row * N + col] =
                make_float2(acc[i][j][0], acc[i][j][1]);
            *(float2*)&C[(size_t)(row + 8) * N + col] =
                make_float2(acc[i][j][2], acc[i][j][3]);
        }
    }
}

// ---------------------------------------------------------------------------
// RoPE in-place on g_Q (32 heads) and g_K (8 heads).
// ---------------------------------------------------------------------------
__global__ __launch_bounds__(64) void rope_kernel()
{
    const int s = blockIdx.x;
    const int h = blockIdx.y;
    const int i = threadIdx.x;   // 0..63

    float* p;
    if (h < NH) p = &g_Q[(size_t)s * HID + h * HD];
    else        p = &g_K[(size_t)s * KVDIM + (h - NH) * HD];

    float freq = __powf(10000.0f, -((float)(2 * i)) / 128.0f);
    float ang  = (float)s * freq;
    float sn, c;
    sincosf(ang, &sn, &c);

    float x1 = p[i];
    float x2 = p[i + 64];
    p[i]      = x1 * c - x2 * sn;
    p[i + 64] = x2 * c + x1 * sn;
}

// ---------------------------------------------------------------------------
// Flash attention (causal, GQA 4:1) — fp32 SIMT (tensorize next round).
// ---------------------------------------------------------------------------
__global__ __launch_bounds__(256) void flash_attn()
{
    extern __shared__ float sm[];
    float* Qs   = sm;
    float* Ks   = Qs + 64 * 128;
    float* Ss   = Ks + 64 * 128;
    float* mrow = Ss + 64 * 64;
    float* lrow = mrow + 64;
    float* fac  = lrow + 64;

    const int qt  = blockIdx.x;
    const int h   = blockIdx.y;
    const int kvh = h >> 2;
    const int tid = threadIdx.x;
    const int tx  = tid & 15;
    const int ty  = tid >> 4;

#pragma unroll
    for (int t = 0; t < 8; t++) {
        int idx = tid + t * 256;
        int row = idx >> 5;
        int d4  = (idx & 31) << 2;
        *(float4*)&Qs[row * 128 + d4] =
            *(const float4*)&g_Q[(size_t)(qt * 64 + row) * HID + h * HD + d4];
    }
    if (tid < 64) { mrow[tid] = -INFINITY; lrow[tid] = 0.f; }

    float o[4][8];
#pragma unroll
    for (int i = 0; i < 4; i++)
#pragma unroll
        for (int j = 0; j < 8; j++) o[i][j] = 0.f;

    __syncthreads();

    const float scale = 0.08838834764831845f;

    for (int jt = 0; jt <= qt; jt++) {
#pragma unroll
        for (int t = 0; t < 8; t++) {
            int idx = tid + t * 256;
            int row = idx >> 5;
            int d4  = (idx & 31) << 2;
            *(float4*)&Ks[row * 128 + d4] =
                *(const float4*)&g_K[(size_t)(jt * 64 + row) * KVDIM + kvh * HD + d4];
        }
        __syncthreads();

        float s4[4][4];
#pragma unroll
        for (int i = 0; i < 4; i++)
#pragma unroll
            for (int j = 0; j < 4; j++) s4[i][j] = 0.f;

        for (int d = 0; d < 128; d += 4) {
            float4 qv[4], kv[4];
#pragma unroll
            for (int i = 0; i < 4; i++)
                qv[i] = *(const float4*)&Qs[(ty * 4 + i) * 128 + d];
#pragma unroll
            for (int j = 0; j < 4; j++)
                kv[j] = *(const float4*)&Ks[(tx * 4 + j) * 128 + d];
#pragma unroll
            for (int i = 0; i < 4; i++)
#pragma unroll
                for (int j = 0; j < 4; j++) {
                    s4[i][j] = fmaf(qv[i].x, kv[j].x, s4[i][j]);
                    s4[i][j] = fmaf(qv[i].y, kv[j].y, s4[i][j]);
                    s4[i][j] = fmaf(qv[i].z, kv[j].z, s4[i][j]);
                    s4[i][j] = fmaf(qv[i].w, kv[j].w, s4[i][j]);
                }
        }

#pragma unroll
        for (int i = 0; i < 4; i++)
#pragma unroll
            for (int j = 0; j < 4; j++) {
                float v = s4[i][j] * scale;
                int rg = qt * 64 + ty * 4 + i;
                int cg = jt * 64 + tx * 4 + j;
                if (cg > rg) v = -INFINITY;
                Ss[(ty * 4 + i) * 64 + tx * 4 + j] = v;
            }
        __syncthreads();

        if (tid < 64) {
            int r = tid;
            float mo = mrow[r];
            float mx = mo;
#pragma unroll 8
            for (int c = 0; c < 64; c++) mx = fmaxf(mx, Ss[r * 64 + c]);
            float sum = 0.f;
#pragma unroll 8
            for (int c = 0; c < 64; c++) {
                float e = __expf(Ss[r * 64 + c] - mx);
                Ss[r * 64 + c] = e;
                sum += e;
            }
            float f = (mo == -INFINITY) ? 0.f : __expf(mo - mx);
            lrow[r] = lrow[r] * f + sum;
            mrow[r] = mx;
            fac[r]  = f;
        }
        __syncthreads();

#pragma unroll
        for (int t = 0; t < 8; t++) {
            int idx = tid + t * 256;
            int row = idx >> 5;
            int d4  = (idx & 31) << 2;
            *(float4*)&Ks[row * 128 + d4] =
                *(const float4*)&g_V[(size_t)(jt * 64 + row) * KVDIM + kvh * HD + d4];
        }
#pragma unroll
        for (int i = 0; i < 4; i++) {
            float f = fac[ty * 4 + i];
#pragma unroll
            for (int j = 0; j < 8; j++) o[i][j] *= f;
        }
        __syncthreads();

        for (int kk = 0; kk < 64; kk += 4) {
            float4 p4[4];
#pragma unroll
            for (int i = 0; i < 4; i++)
                p4[i] = *(const float4*)&Ss[(ty * 4 + i) * 64 + kk];
#pragma unroll
            for (int u = 0; u < 4; u++) {
                float4 v0 = *(const float4*)&Ks[(kk + u) * 128 + tx * 8];
                float4 v1 = *(const float4*)&Ks[(kk + u) * 128 + tx * 8 + 4];
#pragma unroll
                for (int i = 0; i < 4; i++) {
                    float p = (u == 0) ? p4[i].x : (u == 1) ? p4[i].y
                             : (u == 2) ? p4[i].z : p4[i].w;
                    o[i][0] = fmaf(p, v0.x, o[i][0]);
                    o[i][1] = fmaf(p, v0.y, o[i][1]);
                    o[i][2] = fmaf(p, v0.z, o[i][2]);
                    o[i][3] = fmaf(p, v0.w, o[i][3]);
                    o[i][4] = fmaf(p, v1.x, o[i][4]);
                    o[i][5] = fmaf(p, v1.y, o[i][5]);
                    o[i][6] = fmaf(p, v1.z, o[i][6]);
                    o[i][7] = fmaf(p, v1.w, o[i][7]);
                }
            }
        }
        __syncthreads();
    }

#pragma unroll
    for (int i = 0; i < 4; i++) {
        float inv = 1.f / lrow[ty * 4 + i];
        float* dst = &g_A[(size_t)(qt * 64 + ty * 4 + i) * HID + h * HD + tx * 8];
        float4 v0 = make_float4(o[i][0] * inv, o[i][1] * inv, o[i][2] * inv, o[i][3] * inv);
        float4 v1 = make_float4(o[i][4] * inv, o[i][5] * inv, o[i][6] * inv, o[i][7] * inv);
        *(float4*)dst       = v0;
        *(float4*)(dst + 4) = v1;
    }
}

// ---------------------------------------------------------------------------
extern "C" void kernel_launch(void* const* d_in, const int* in_sizes, int n_in,
                              void* d_out, int out_size)
{
    const float* X  = (const float*)d_in[0];
    const float* Wq = (const float*)d_in[1];
    const float* Wk = (const float*)d_in[2];
    const float* Wv = (const float*)d_in[3];
    const float* Wo = (const float*)d_in[4];
    float* out = (float*)d_out;

    float *Qp, *Kp, *Vp, *Ap;
    cudaGetSymbolAddress((void**)&Qp, g_Q);
    cudaGetSymbolAddress((void**)&Kp, g_K);
    cudaGetSymbolAddress((void**)&Vp, g_V);
    cudaGetSymbolAddress((void**)&Ap, g_A);
    bf16 *Xh, *Xl, *Wqh, *Wql, *Wkh, *Wkl, *Wvh, *Wvl, *Woh, *Wol, *Ahp, *Alp;
    cudaGetSymbolAddress((void**)&Xh,  g_Xh);  cudaGetSymbolAddress((void**)&Xl,  g_Xl);
    cudaGetSymbolAddress((void**)&Wqh, g_Wqh); cudaGetSymbolAddress((void**)&Wql, g_Wql);
    cudaGetSymbolAddress((void**)&Wkh, g_Wkh); cudaGetSymbolAddress((void**)&Wkl, g_Wkl);
    cudaGetSymbolAddress((void**)&Wvh, g_Wvh); cudaGetSymbolAddress((void**)&Wvl, g_Wvl);
    cudaGetSymbolAddress((void**)&Woh, g_Woh); cudaGetSymbolAddress((void**)&Wol, g_Wol);
    cudaGetSymbolAddress((void**)&Ahp, g_Ah);  cudaGetSymbolAddress((void**)&Alp, g_Al);

    cudaFuncSetAttribute(gemm_mma, cudaFuncAttributeMaxDynamicSharedMemorySize, GEMM_SMEM);

    // split fp32 -> bf16 hi/lo
    const int nX  = S_LEN * HID / 4;
    const int nWq = HID * HID / 4;
    const int nWk = KVDIM * HID / 4;
    split_kernel<<<nX / 256, 256>>>((const float4*)X, (__nv_bfloat162*)Xh, (__nv_bfloat162*)Xl, nX);
    split_kernel<<<nWq / 256, 256>>>((const float4*)Wq, (__nv_bfloat162*)Wqh, (__nv_bfloat162*)Wql, nWq);
    split_kernel<<<nWk / 256, 256>>>((const float4*)Wk, (__nv_bfloat162*)Wkh, (__nv_bfloat162*)Wkl, nWk);
    split_kernel<<<nWk / 256, 256>>>((const float4*)Wv, (__nv_bfloat162*)Wvh, (__nv_bfloat162*)Wvl, nWk);
    split_kernel<<<nWq / 256, 256>>>((const float4*)Wo, (__nv_bfloat162*)Woh, (__nv_bfloat162*)Wol, nWq);

    // QKV projections on HMMA tensor cores
    gemm_mma<<<dim3(HID / BN, S_LEN / BM), 256, GEMM_SMEM>>>(Xh, Xl, Wqh, Wql, Qp, S_LEN, HID, HID);
    gemm_mma<<<dim3(KVDIM / BN, S_LEN / BM), 256, GEMM_SMEM>>>(Xh, Xl, Wkh, Wkl, Kp, S_LEN, KVDIM, HID);
    gemm_mma<<<dim3(KVDIM / BN, S_LEN / BM), 256, GEMM_SMEM>>>(Xh, Xl, Wvh, Wvl, Vp, S_LEN, KVDIM, HID);

    // RoPE
    rope_kernel<<<dim3(S_LEN, NH + NKV), 64>>>();

    // Flash attention (fp32)
    const int flash_smem = (64 * 128 * 2 + 64 * 64 + 3 * 64) * (int)sizeof(float);
    cudaFuncSetAttribute(flash_attn, cudaFuncAttributeMaxDynamicSharedMemorySize, flash_smem);
    flash_attn<<<dim3(S_LEN / 64, NH), 256, flash_smem>>>();

    // split attention output, then O projection
    split_kernel<<<nX / 256, 256>>>((const float4*)Ap, (__nv_bfloat162*)Ahp, (__nv_bfloat162*)Alp, nX);
    gemm_mma<<<dim3(HID / BN, S_LEN / BM), 256, GEMM_SMEM>>>(Ahp, Alp, Woh, Wol, out, S_LEN, HID, HID);
}

// round 5
// speedup vs baseline: 4.5495x; 3.5198x over previous
#include <cuda_runtime.h>
#include <cuda_bf16.h>
#include <cstdint>
#include <math.h>

#define S_LEN 2048
#define HID   4096
#define NH    32
#define NKV   8
#define HD    128
#define KVDIM (NKV * HD)   // 1024

typedef __nv_bfloat16 bf16;

// ------------------------- device scratch (no allocs allowed) --------------
__device__ float g_Q[(size_t)S_LEN * HID];
__device__ float g_K[(size_t)S_LEN * KVDIM];
__device__ float g_V[(size_t)S_LEN * KVDIM];
__device__ float g_A[(size_t)S_LEN * HID];

__device__ bf16 g_Xh[S_LEN * HID],  g_Xl[S_LEN * HID];
__device__ bf16 g_Wqh[HID * HID],   g_Wql[HID * HID];
__device__ bf16 g_Wkh[KVDIM * HID], g_Wkl[KVDIM * HID];
__device__ bf16 g_Wvh[KVDIM * HID], g_Wvl[KVDIM * HID];
__device__ bf16 g_Woh[HID * HID],   g_Wol[HID * HID];
__device__ bf16 g_Ah[S_LEN * HID],  g_Al[S_LEN * HID];
// bf16 splits of Q/K/V for tensor-core attention
__device__ bf16 g_Qbh[S_LEN * HID],  g_Qbl[S_LEN * HID];
__device__ bf16 g_Kbh[S_LEN * KVDIM], g_Kbl[S_LEN * KVDIM];
__device__ bf16 g_Vbh[S_LEN * KVDIM], g_Vbl[S_LEN * KVDIM];

// ------------------------- PTX helpers (sm_80-class only) -------------------
__device__ __forceinline__ uint32_t smem_u32(const void* p) {
    uint32_t a;
    asm("{ .reg .u64 t; cvta.to.shared.u64 t, %1; cvt.u32.u64 %0, t; }" : "=r"(a) : "l"(p));
    return a;
}
#define CP_ASYNC16(dst, src) \
    asm volatile("cp.async.cg.shared.global [%0], [%1], 16;" :: "r"(dst), "l"(src) : "memory")
#define CP_COMMIT()  asm volatile("cp.async.commit_group;" ::: "memory")
#define CP_WAIT2()   asm volatile("cp.async.wait_group 2;" ::: "memory")
#define CP_WAIT0()   asm volatile("cp.async.wait_group 0;" ::: "memory")

#define LDSM4(r0, r1, r2, r3, addr) \
    asm volatile("ldmatrix.sync.aligned.m8n8.x4.shared.b16 {%0,%1,%2,%3}, [%4];" \
                 : "=r"(r0), "=r"(r1), "=r"(r2), "=r"(r3) : "r"(addr))
#define LDSM4T(r0, r1, r2, r3, addr) \
    asm volatile("ldmatrix.sync.aligned.m8n8.x4.trans.shared.b16 {%0,%1,%2,%3}, [%4];" \
                 : "=r"(r0), "=r"(r1), "=r"(r2), "=r"(r3) : "r"(addr))

__device__ __forceinline__ void mma16816(float* c, const uint32_t* a,
                                         uint32_t b0, uint32_t b1) {
    asm volatile(
        "mma.sync.aligned.m16n8k16.row.col.f32.bf16.bf16.f32 "
        "{%0,%1,%2,%3}, {%4,%5,%6,%7}, {%8,%9}, {%0,%1,%2,%3};"
        : "+f"(c[0]), "+f"(c[1]), "+f"(c[2]), "+f"(c[3])
        : "r"(a[0]), "r"(a[1]), "r"(a[2]), "r"(a[3]), "r"(b0), "r"(b1));
}

// swizzles: 128B-row tiles (row bits 7-9 -> 4-6), 256B-row tiles (bits 8-10 -> 4-6)
#define SWZ(o)  ((o) ^ (((o) >> 3) & 0x70))
#define SWZV(o) ((o) ^ (((o) >> 4) & 0x70))

__device__ __forceinline__ uint32_t pack_bf16x2(float a, float b) {
    __nv_bfloat162 t = __halves2bfloat162(__float2bfloat16(a), __float2bfloat16(b));
    return *reinterpret_cast<uint32_t*>(&t);
}

// ------------------------- split fp32 -> bf16 hi/lo -------------------------
__global__ __launch_bounds__(256) void split_kernel(const float4* __restrict__ src,
                                                    __nv_bfloat162* __restrict__ hi,
                                                    __nv_bfloat162* __restrict__ lo,
                                                    int n4)
{
    int i = blockIdx.x * 256 + threadIdx.x;
    if (i >= n4) return;
    float4 v = src[i];
    bf16 h0 = __float2bfloat16(v.x), h1 = __float2bfloat16(v.y);
    bf16 h2 = __float2bfloat16(v.z), h3 = __float2bfloat16(v.w);
    bf16 l0 = __float2bfloat16(v.x - __bfloat162float(h0));
    bf16 l1 = __float2bfloat16(v.y - __bfloat162float(h1));
    bf16 l2 = __float2bfloat16(v.z - __bfloat162float(h2));
    bf16 l3 = __float2bfloat16(v.w - __bfloat162float(h3));
    hi[2 * i]     = __halves2bfloat162(h0, h1);
    hi[2 * i + 1] = __halves2bfloat162(h2, h3);
    lo[2 * i]     = __halves2bfloat162(l0, l1);
    lo[2 * i + 1] = __halves2bfloat162(l2, l3);
}

// ------------------------- fused 3-term HMMA GEMM: C = A*B^T ----------------
// A[M,K], B[N,K] row-major (hi/lo pairs). BM=BN=128, BK=64 elems (128B rows).
// Per chunk: load Ah,Al,Bh,Bl once; acc += AhBh + AlBh + AhBl.
#define BM 128
#define BN 128
#define BKE 64
#define TILE_B 16384              // 128 rows * 128 B
#define G_AH 0
#define G_AL 16384
#define G_BH 32768
#define G_BL 49152
#define STG  65536
#define NST  3
#define GEMM_SMEM (NST * STG)

__device__ __forceinline__ void issue_loads_g(int j, int tid, int m0, int n0, int K,
                                              const bf16* Ah, const bf16* Al,
                                              const bf16* Bh, const bf16* Bl,
                                              uint32_t sbase)
{
    int k0 = j * BKE;
    uint32_t st = sbase + (j % NST) * STG;
#pragma unroll
    for (int t = 0; t < 4; t++) {
        int idx = tid + t * 256;              // 0..1023
        int row = idx >> 3;                   // 0..127
        int ch  = idx & 7;                    // 16B chunk (8 per 128B row)
        uint32_t off = SWZ((uint32_t)(row * 128 + ch * 16));
        size_t gsrcA = (size_t)(m0 + row) * K + k0 + ch * 8;
        size_t gsrcB = (size_t)(n0 + row) * K + k0 + ch * 8;
        CP_ASYNC16(st + G_AH + off, Ah + gsrcA);
        CP_ASYNC16(st + G_AL + off, Al + gsrcA);
        CP_ASYNC16(st + G_BH + off, Bh + gsrcB);
        CP_ASYNC16(st + G_BL + off, Bl + gsrcB);
    }
}

__global__ __launch_bounds__(256, 1) void gemm_mma(const bf16* __restrict__ Ah,
                                                   const bf16* __restrict__ Al,
                                                   const bf16* __restrict__ Bh,
                                                   const bf16* __restrict__ Bl,
                                                   float* __restrict__ C,
                                                   int M, int N, int K)
{
    extern __shared__ char smem[];
    const uint32_t sbase = smem_u32(smem);
    const int tid  = threadIdx.x;
    const int lane = tid & 31;
    const int wid  = tid >> 5;
    const int wm   = wid & 3;     // 4 warps in M (32 rows each)
    const int wn   = wid >> 2;    // 2 warps in N (64 cols each)
    const int m0 = blockIdx.y * BM;
    const int n0 = blockIdx.x * BN;
    const int kchunks = K / BKE;

    float acc[2][8][4];
#pragma unroll
    for (int i = 0; i < 2; i++)
#pragma unroll
        for (int j = 0; j < 8; j++)
#pragma unroll
            for (int r = 0; r < 4; r++) acc[i][j][r] = 0.f;

    uint32_t arowr[2], browr[4];
#pragma unroll
    for (int i = 0; i < 2; i++)
        arowr[i] = (uint32_t)((wm * 32 + i * 16 + (lane & 15)) * 128 + (lane >> 4) * 16);
#pragma unroll
    for (int p = 0; p < 4; p++)
        browr[p] = (uint32_t)((wn * 64 + p * 16 + (lane & 7) + ((lane >> 4) << 3)) * 128 +
                              ((lane >> 3) & 1) * 16);

    // prologue: 3 stages
    for (int j = 0; j < 3 && j < kchunks; j++) {
        issue_loads_g(j, tid, m0, n0, K, Ah, Al, Bh, Bl, sbase);
        CP_COMMIT();
    }

    for (int it = 0; it < kchunks; it++) {
        uint32_t st = sbase + (it % NST) * STG;
        CP_WAIT2();
        __syncthreads();

#pragma unroll
        for (int ks = 0; ks < 4; ks++) {
            uint32_t kb = ks * 32;
            uint32_t ah[2][4], al[2][4], bh[4][4], bl[4][4];
#pragma unroll
            for (int i = 0; i < 2; i++) {
                uint32_t off = SWZ(arowr[i] + kb);
                LDSM4(ah[i][0], ah[i][1], ah[i][2], ah[i][3], st + G_AH + off);
                LDSM4(al[i][0], al[i][1], al[i][2], al[i][3], st + G_AL + off);
            }
#pragma unroll
            for (int p = 0; p < 4; p++) {
                uint32_t off = SWZ(browr[p] + kb);
                LDSM4(bh[p][0], bh[p][1], bh[p][2], bh[p][3], st + G_BH + off);
                LDSM4(bl[p][0], bl[p][1], bl[p][2], bl[p][3], st + G_BL + off);
            }
#pragma unroll
            for (int i = 0; i < 2; i++)
#pragma unroll
                for (int j = 0; j < 8; j++) {
                    int p = j >> 1;
                    int h = (j & 1) << 1;
                    mma16816(acc[i][j], ah[i], bh[p][h], bh[p][h + 1]);
                    mma16816(acc[i][j], al[i], bh[p][h], bh[p][h + 1]);
                    mma16816(acc[i][j], ah[i], bl[p][h], bl[p][h + 1]);
                }
        }
        __syncthreads();

        int nj = it + 3;
        if (nj < kchunks)
            issue_loads_g(nj, tid, m0, n0, K, Ah, Al, Bh, Bl, sbase);
        CP_COMMIT();
    }

    const int g   = lane >> 2;
    const int tig = lane & 3;
#pragma unroll
    for (int i = 0; i < 2; i++) {
        int row = m0 + wm * 32 + i * 16 + g;
#pragma unroll
        for (int j = 0; j < 8; j++) {
            int col = n0 + wn * 64 + j * 8 + 2 * tig;
            *(float2*)&C[(size_t)row * N + col] =
                make_float2(acc[i][j][0], acc[i][j][1]);
            *(float2*)&C[(size_t)(row + 8) * N + col] =
                make_float2(acc[i][j][2], acc[i][j][3]);
        }
    }
}

// ---------------------------------------------------------------------------
// RoPE in-place on g_Q (32 heads) and g_K (8 heads).
// ---------------------------------------------------------------------------
__global__ __launch_bounds__(64) void rope_kernel()
{
    const int s = blockIdx.x;
    const int h = blockIdx.y;
    const int i = threadIdx.x;

    float* p;
    if (h < NH) p = &g_Q[(size_t)s * HID + h * HD];
    else        p = &g_K[(size_t)s * KVDIM + (h - NH) * HD];

    float freq = __powf(10000.0f, -((float)(2 * i)) / 128.0f);
    float ang  = (float)s * freq;
    float sn, c;
    sincosf(ang, &sn, &c);

    float x1 = p[i];
    float x2 = p[i + 64];
    p[i]      = x1 * c - x2 * sn;
    p[i + 64] = x2 * c + x1 * sn;
}

// ---------------------------------------------------------------------------
// HMMA flash attention (causal, GQA 4:1), split-bf16 3-term everywhere.
// Block = (128-row q tile, head). 8 warps x 16 rows. KV tile = 64.
// ---------------------------------------------------------------------------
#define F_QH 0
#define F_QL 32768
#define F_KH 65536
#define F_KL 81920
#define F_VH 98304
#define F_VL 114688
#define FLASH_SMEM 131072

__global__ __launch_bounds__(256, 1) void flash_mma()
{
    extern __shared__ char smem[];
    const uint32_t sbase = smem_u32(smem);
    const int tid  = threadIdx.x;
    const int lane = tid & 31;
    const int wid  = tid >> 5;
    const int qt   = blockIdx.x;         // 0..15
    const int h    = blockIdx.y;         // 0..31
    const int kvh  = h >> 2;
    const int q0   = qt * 128;
    const int g    = lane >> 2;
    const int tig  = lane & 3;

    // --- load Q tiles (hi/lo), 128 rows x 128 bf16 (256B rows, SWZV) ---
#pragma unroll
    for (int t = 0; t < 16; t++) {
        int idx = tid + t * 256;          // 0..4095
        int tile = idx >> 11;             // 0: hi, 1: lo
        int r    = (idx >> 4) & 127;
        int ch   = idx & 15;
        uint32_t off = SWZV((uint32_t)(r * 256 + ch * 16));
        const bf16* src = (tile ? g_Qbl : g_Qbh) +
                          (size_t)(q0 + r) * HID + h * HD + ch * 8;
        CP_ASYNC16(sbase + (tile ? F_QL : F_QH) + off, src);
    }
    CP_COMMIT();

    float of[16][4];
#pragma unroll
    for (int nt = 0; nt < 16; nt++)
#pragma unroll
        for (int r = 0; r < 4; r++) of[nt][r] = 0.f;
    float m0 = -INFINITY, m1 = -INFINITY, l0 = 0.f, l1 = 0.f;

    const float scale = 0.08838834764831845f;
    const int rg0 = q0 + wid * 16 + g;
    const int rg1 = rg0 + 8;
    const int ntiles = 2 * qt + 2;

    uint32_t aoffQ = (uint32_t)((wid * 16 + (lane & 15)) * 256 + (lane >> 4) * 16);
    uint32_t boffK[4];
#pragma unroll
    for (int p = 0; p < 4; p++)
        boffK[p] = (uint32_t)((p * 16 + (lane & 7) + ((lane >> 4) << 3)) * 256 +
                              ((lane >> 3) & 1) * 16);
    uint32_t voffr = (uint32_t)(((lane & 7) + ((lane >> 3) & 1) * 8) * 256 +
                                (lane >> 4) * 16);

    for (int jt = 0; jt < ntiles; jt++) {
        // --- load K/V tiles (hi/lo): 4 x [64 rows x 256B] ---
#pragma unroll
        for (int t = 0; t < 16; t++) {
            int idx = tid + t * 256;       // 0..4095
            int tile = idx >> 10;          // 0:Kh 1:Kl 2:Vh 3:Vl
            int r    = (idx >> 4) & 63;
            int ch   = idx & 15;
            uint32_t off = SWZV((uint32_t)(r * 256 + ch * 16));
            const bf16* base = (tile == 0) ? g_Kbh : (tile == 1) ? g_Kbl
                             : (tile == 2) ? g_Vbh : g_Vbl;
            uint32_t soff = (tile == 0) ? F_KH : (tile == 1) ? F_KL
                          : (tile == 2) ? F_VH : F_VL;
            CP_ASYNC16(sbase + soff + off,
                       base + (size_t)(jt * 64 + r) * KVDIM + kvh * HD + ch * 8);
        }
        CP_COMMIT();
        CP_WAIT0();
        __syncthreads();

        // --- S = Qh*Kh^T + Ql*Kh^T + Qh*Kl^T ---
        float sfrag[8][4];
#pragma unroll
        for (int j = 0; j < 8; j++)
#pragma unroll
            for (int r = 0; r < 4; r++) sfrag[j][r] = 0.f;

#pragma unroll
        for (int ks = 0; ks < 8; ks++) {
            uint32_t kb = ks * 32;
            uint32_t qh[4], ql[4], kh[4][4], kl[4][4];
            uint32_t qo = SWZV(aoffQ + kb);
            LDSM4(qh[0], qh[1], qh[2], qh[3], sbase + F_QH + qo);
            LDSM4(ql[0], ql[1], ql[2], ql[3], sbase + F_QL + qo);
#pragma unroll
            for (int p = 0; p < 4; p++) {
                uint32_t ko = SWZV(boffK[p] + kb);
                LDSM4(kh[p][0], kh[p][1], kh[p][2], kh[p][3], sbase + F_KH + ko);
                LDSM4(kl[p][0], kl[p][1], kl[p][2], kl[p][3], sbase + F_KL + ko);
            }
#pragma unroll
            for (int j = 0; j < 8; j++) {
                int p = j >> 1;
                int hs = (j & 1) << 1;
                mma16816(sfrag[j], qh, kh[p][hs], kh[p][hs + 1]);
                mma16816(sfrag[j], ql, kh[p][hs], kh[p][hs + 1]);
                mma16816(sfrag[j], qh, kl[p][hs], kl[p][hs + 1]);
            }
        }

        // --- scale + causal mask ---
#pragma unroll
        for (int j = 0; j < 8; j++) {
            int cg = jt * 64 + j * 8 + 2 * tig;
            float c0 = sfrag[j][0] * scale; if (cg     > rg0) c0 = -INFINITY;
            float c1 = sfrag[j][1] * scale; if (cg + 1 > rg0) c1 = -INFINITY;
            float c2 = sfrag[j][2] * scale; if (cg     > rg1) c2 = -INFINITY;
            float c3 = sfrag[j][3] * scale; if (cg + 1 > rg1) c3 = -INFINITY;
            sfrag[j][0] = c0; sfrag[j][1] = c1; sfrag[j][2] = c2; sfrag[j][3] = c3;
        }

        // --- online softmax (rows g, g+8; quad shfl reduce) ---
        float mx0 = -INFINITY, mx1 = -INFINITY;
#pragma unroll
        for (int j = 0; j < 8; j++) {
            mx0 = fmaxf(mx0, fmaxf(sfrag[j][0], sfrag[j][1]));
            mx1 = fmaxf(mx1, fmaxf(sfrag[j][2], sfrag[j][3]));
        }
        mx0 = fmaxf(mx0, __shfl_xor_sync(0xffffffffu, mx0, 1));
        mx0 = fmaxf(mx0, __shfl_xor_sync(0xffffffffu, mx0, 2));
        mx1 = fmaxf(mx1, __shfl_xor_sync(0xffffffffu, mx1, 1));
        mx1 = fmaxf(mx1, __shfl_xor_sync(0xffffffffu, mx1, 2));
        float mn0 = fmaxf(m0, mx0);
        float mn1 = fmaxf(m1, mx1);
        float f0 = __expf(m0 - mn0);
        float f1 = __expf(m1 - mn1);

        uint32_t ph0[8], ph1[8], pl0[8], pl1[8];
        float s0 = 0.f, s1 = 0.f;
#pragma unroll
        for (int j = 0; j < 8; j++) {
            float e0 = __expf(sfrag[j][0] - mn0);
            float e1 = __expf(sfrag[j][1] - mn0);
            float e2 = __expf(sfrag[j][2] - mn1);
            float e3 = __expf(sfrag[j][3] - mn1);
            s0 += e0 + e1; s1 += e2 + e3;
            bf16 h0 = __float2bfloat16(e0), h1b = __float2bfloat16(e1);
            bf16 h2 = __float2bfloat16(e2), h3b = __float2bfloat16(e3);
            ph0[j] = pack_bf16x2(e0, e1);      // exact bf16 re-pack of h0,h1
            ph1[j] = pack_bf16x2(e2, e3);
            pl0[j] = pack_bf16x2(e0 - __bfloat162float(h0), e1 - __bfloat162float(h1b));
            pl1[j] = pack_bf16x2(e2 - __bfloat162float(h2), e3 - __bfloat162float(h3b));
        }
        s0 += __shfl_xor_sync(0xffffffffu, s0, 1);
        s0 += __shfl_xor_sync(0xffffffffu, s0, 2);
        s1 += __shfl_xor_sync(0xffffffffu, s1, 1);
        s1 += __shfl_xor_sync(0xffffffffu, s1, 2);
        l0 = l0 * f0 + s0;
        l1 = l1 * f1 + s1;
        m0 = mn0; m1 = mn1;
#pragma unroll
        for (int nt = 0; nt < 16; nt++) {
            of[nt][0] *= f0; of[nt][1] *= f0;
            of[nt][2] *= f1; of[nt][3] *= f1;
        }

        // --- O += Ph*Vh + Pl*Vh + Ph*Vl  (V via ldmatrix.trans) ---
#pragma unroll
        for (int kk = 0; kk < 4; kk++) {
            uint32_t ah[4] = {ph0[2 * kk], ph1[2 * kk], ph0[2 * kk + 1], ph1[2 * kk + 1]};
            uint32_t al[4] = {pl0[2 * kk], pl1[2 * kk], pl0[2 * kk + 1], pl1[2 * kk + 1]};
#pragma unroll
            for (int np = 0; np < 8; np++) {
                uint32_t off = SWZV((uint32_t)(kk * 16 * 256) + voffr + (uint32_t)(np * 32));
                uint32_t vh0, vh1, vh2, vh3, vl0, vl1, vl2, vl3;
                LDSM4T(vh0, vh1, vh2, vh3, sbase + F_VH + off);
                LDSM4T(vl0, vl1, vl2, vl3, sbase + F_VL + off);
                mma16816(of[2 * np],     ah, vh0, vh1);
                mma16816(of[2 * np + 1], ah, vh2, vh3);
                mma16816(of[2 * np],     al, vh0, vh1);
                mma16816(of[2 * np + 1], al, vh2, vh3);
                mma16816(of[2 * np],     ah, vl0, vl1);
                mma16816(of[2 * np + 1], ah, vl2, vl3);
            }
        }
        __syncthreads();
    }

    // --- normalize + store ---
    float inv0 = 1.f / l0;
    float inv1 = 1.f / l1;
#pragma unroll
    for (int nt = 0; nt < 16; nt++) {
        int col = h * HD + nt * 8 + 2 * tig;
        *(float2*)&g_A[(size_t)rg0 * HID + col] =
            make_float2(of[nt][0] * inv0, of[nt][1] * inv0);
        *(float2*)&g_A[(size_t)rg1 * HID + col] =
            make_float2(of[nt][2] * inv1, of[nt][3] * inv1);
    }
}

// ---------------------------------------------------------------------------
extern "C" void kernel_launch(void* const* d_in, const int* in_sizes, int n_in,
                              void* d_out, int out_size)
{
    const float* X  = (const float*)d_in[0];
    const float* Wq = (const float*)d_in[1];
    const float* Wk = (const float*)d_in[2];
    const float* Wv = (const float*)d_in[3];
    const float* Wo = (const float*)d_in[4];
    float* out = (float*)d_out;

    float *Qp, *Kp, *Vp, *Ap;
    cudaGetSymbolAddress((void**)&Qp, g_Q);
    cudaGetSymbolAddress((void**)&Kp, g_K);
    cudaGetSymbolAddress((void**)&Vp, g_V);
    cudaGetSymbolAddress((void**)&Ap, g_A);
    bf16 *Xh, *Xl, *Wqh, *Wql, *Wkh, *Wkl, *Wvh, *Wvl, *Woh, *Wol, *Ahp, *Alp;
    bf16 *Qbh, *Qbl, *Kbh, *Kbl, *Vbh, *Vbl;
    cudaGetSymbolAddress((void**)&Xh,  g_Xh);  cudaGetSymbolAddress((void**)&Xl,  g_Xl);
    cudaGetSymbolAddress((void**)&Wqh, g_Wqh); cudaGetSymbolAddress((void**)&Wql, g_Wql);
    cudaGetSymbolAddress((void**)&Wkh, g_Wkh); cudaGetSymbolAddress((void**)&Wkl, g_Wkl);
    cudaGetSymbolAddress((void**)&Wvh, g_Wvh); cudaGetSymbolAddress((void**)&Wvl, g_Wvl);
    cudaGetSymbolAddress((void**)&Woh, g_Woh); cudaGetSymbolAddress((void**)&Wol, g_Wol);
    cudaGetSymbolAddress((void**)&Ahp, g_Ah);  cudaGetSymbolAddress((void**)&Alp, g_Al);
    cudaGetSymbolAddress((void**)&Qbh, g_Qbh); cudaGetSymbolAddress((void**)&Qbl, g_Qbl);
    cudaGetSymbolAddress((void**)&Kbh, g_Kbh); cudaGetSymbolAddress((void**)&Kbl, g_Kbl);
    cudaGetSymbolAddress((void**)&Vbh, g_Vbh); cudaGetSymbolAddress((void**)&Vbl, g_Vbl);

    cudaFuncSetAttribute(gemm_mma, cudaFuncAttributeMaxDynamicSharedMemorySize, GEMM_SMEM);
    cudaFuncSetAttribute(flash_mma, cudaFuncAttributeMaxDynamicSharedMemorySize, FLASH_SMEM);

    const int nX  = S_LEN * HID / 4;
    const int nWq = HID * HID / 4;
    const int nWk = KVDIM * HID / 4;
    const int nKV = S_LEN * KVDIM / 4;

    // input splits
    split_kernel<<<nX / 256, 256>>>((const float4*)X, (__nv_bfloat162*)Xh, (__nv_bfloat162*)Xl, nX);
    split_kernel<<<nWq / 256, 256>>>((const float4*)Wq, (__nv_bfloat162*)Wqh, (__nv_bfloat162*)Wql, nWq);
    split_kernel<<<nWk / 256, 256>>>((const float4*)Wk, (__nv_bfloat162*)Wkh, (__nv_bfloat162*)Wkl, nWk);
    split_kernel<<<nWk / 256, 256>>>((const float4*)Wv, (__nv_bfloat162*)Wvh, (__nv_bfloat162*)Wvl, nWk);
    split_kernel<<<nWq / 256, 256>>>((const float4*)Wo, (__nv_bfloat162*)Woh, (__nv_bfloat162*)Wol, nWq);

    // projections
    gemm_mma<<<dim3(HID / BN, S_LEN / BM), 256, GEMM_SMEM>>>(Xh, Xl, Wqh, Wql, Qp, S_LEN, HID, HID);
    gemm_mma<<<dim3(KVDIM / BN, S_LEN / BM), 256, GEMM_SMEM>>>(Xh, Xl, Wkh, Wkl, Kp, S_LEN, KVDIM, HID);
    gemm_mma<<<dim3(KVDIM / BN, S_LEN / BM), 256, GEMM_SMEM>>>(Xh, Xl, Wvh, Wvl, Vp, S_LEN, KVDIM, HID);

    // rope then Q/K/V splits for tensor attention
    rope_kernel<<<dim3(S_LEN, NH + NKV), 64>>>();
    split_kernel<<<nX / 256, 256>>>((const float4*)Qp, (__nv_bfloat162*)Qbh, (__nv_bfloat162*)Qbl, nX);
    split_kernel<<<nKV / 256, 256>>>((const float4*)Kp, (__nv_bfloat162*)Kbh, (__nv_bfloat162*)Kbl, nKV);
    split_kernel<<<nKV / 256, 256>>>((const float4*)Vp, (__nv_bfloat162*)Vbh, (__nv_bfloat162*)Vbl, nKV);

    // attention
    flash_mma<<<dim3(S_LEN / 128, NH), 256, FLASH_SMEM>>>();

    // O projection
    split_kernel<<<nX / 256, 256>>>((const float4*)Ap, (__nv_bfloat162*)Ahp, (__nv_bfloat162*)Alp, nX);
    gemm_mma<<<dim3(HID / BN, S_LEN / BM), 256, GEMM_SMEM>>>(Ahp, Alp, Woh, Wol, out, S_LEN, HID, HID);
}

// round 6
// speedup vs baseline: 5.3862x; 1.1839x over previous
#include <cuda_runtime.h>
#include <cuda_fp16.h>
#include <cstdint>
#include <math.h>

#define S_LEN 2048
#define HID   4096
#define NH    32
#define NKV   8
#define HD    128
#define KVDIM (NKV * HD)   // 1024

typedef __half h16;

// ------------------------- device scratch (no allocs allowed) --------------
__device__ float g_Q[(size_t)S_LEN * HID];     // fp32 Q (pre-rope)
__device__ float g_K[(size_t)S_LEN * KVDIM];   // fp32 K (pre-rope)

__device__ h16 g_Xh[S_LEN * HID],  g_Xl[S_LEN * HID];
__device__ h16 g_Wqh[HID * HID],   g_Wql[HID * HID];
__device__ h16 g_Wkh[KVDIM * HID], g_Wkl[KVDIM * HID];
__device__ h16 g_Wv16[KVDIM * HID];
__device__ h16 g_Wo16[HID * HID];
__device__ h16 g_Qh[S_LEN * HID],   g_Ql[S_LEN * HID];    // post-rope split
__device__ h16 g_Kh[S_LEN * KVDIM], g_Kl[S_LEN * KVDIM];  // post-rope split
__device__ h16 g_V16[S_LEN * KVDIM];                      // V single fp16
__device__ h16 g_Ah[S_LEN * HID],   g_Al[S_LEN * HID];    // attn out split

// ------------------------- PTX helpers (sm_80-class only) -------------------
__device__ __forceinline__ uint32_t smem_u32(const void* p) {
    uint32_t a;
    asm("{ .reg .u64 t; cvta.to.shared.u64 t, %1; cvt.u32.u64 %0, t; }" : "=r"(a) : "l"(p));
    return a;
}
#define CP_ASYNC16(dst, src) \
    asm volatile("cp.async.cg.shared.global [%0], [%1], 16;" :: "r"(dst), "l"(src) : "memory")
#define CP_COMMIT()  asm volatile("cp.async.commit_group;" ::: "memory")
#define CP_WAIT2()   asm volatile("cp.async.wait_group 2;" ::: "memory")
#define CP_WAIT1()   asm volatile("cp.async.wait_group 1;" ::: "memory")

#define LDSM4(r0, r1, r2, r3, addr) \
    asm volatile("ldmatrix.sync.aligned.m8n8.x4.shared.b16 {%0,%1,%2,%3}, [%4];" \
                 : "=r"(r0), "=r"(r1), "=r"(r2), "=r"(r3) : "r"(addr))
#define LDSM4T(r0, r1, r2, r3, addr) \
    asm volatile("ldmatrix.sync.aligned.m8n8.x4.trans.shared.b16 {%0,%1,%2,%3}, [%4];" \
                 : "=r"(r0), "=r"(r1), "=r"(r2), "=r"(r3) : "r"(addr))

__device__ __forceinline__ void mma16816(float* c, const uint32_t* a,
                                         uint32_t b0, uint32_t b1) {
    asm volatile(
        "mma.sync.aligned.m16n8k16.row.col.f32.f16.f16.f32 "
        "{%0,%1,%2,%3}, {%4,%5,%6,%7}, {%8,%9}, {%0,%1,%2,%3};"
        : "+f"(c[0]), "+f"(c[1]), "+f"(c[2]), "+f"(c[3])
        : "r"(a[0]), "r"(a[1]), "r"(a[2]), "r"(a[3]), "r"(b0), "r"(b1));
}

// swizzles: 128B-row tiles (bits 7-9 -> 4-6), 256B-row tiles (bits 8-10 -> 4-6)
#define SWZ(o)  ((o) ^ (((o) >> 3) & 0x70))
#define SWZV(o) ((o) ^ (((o) >> 4) & 0x70))

__device__ __forceinline__ uint32_t pack_h2(float a, float b) {
    __half2 t = __floats2half2_rn(a, b);
    return *reinterpret_cast<uint32_t*>(&t);
}

// ------------------------- fp32 -> fp16 hi/lo split -------------------------
__global__ __launch_bounds__(256) void split16_kernel(const float4* __restrict__ src,
                                                      __half2* __restrict__ hi,
                                                      __half2* __restrict__ lo,
                                                      int n4)
{
    int i = blockIdx.x * 256 + threadIdx.x;
    if (i >= n4) return;
    float4 v = src[i];
    h16 h0 = __float2half(v.x), h1 = __float2half(v.y);
    h16 h2 = __float2half(v.z), h3 = __float2half(v.w);
    hi[2 * i]     = __halves2half2(h0, h1);
    hi[2 * i + 1] = __halves2half2(h2, h3);
    lo[2 * i]     = __floats2half2_rn(v.x - __half2float(h0), v.y - __half2float(h1));
    lo[2 * i + 1] = __floats2half2_rn(v.z - __half2float(h2), v.w - __half2float(h3));
}

// ------------------------- fp32 -> fp16 convert -----------------------------
__global__ __launch_bounds__(256) void conv16_kernel(const float4* __restrict__ src,
                                                     __half2* __restrict__ dst,
                                                     int n4)
{
    int i = blockIdx.x * 256 + threadIdx.x;
    if (i >= n4) return;
    float4 v = src[i];
    dst[2 * i]     = __floats2half2_rn(v.x, v.y);
    dst[2 * i + 1] = __floats2half2_rn(v.z, v.w);
}

// ======================== gemm3: C = A*B^T, 3 products ======================
// A split (Ah,Al), B split (Bh,Bl). acc += AhBh + AlBh + AhBl. Out fp32.
#define BM 128
#define BN 128
#define BKE 64
#define G_AH 0
#define G_AL 16384
#define G_BH 32768
#define G_BL 49152
#define STG  65536
#define NST  3
#define GEMM3_SMEM (NST * STG)

__device__ __forceinline__ void issue_loads_g3(int j, int tid, int m0, int n0, int K,
                                               const h16* Ah, const h16* Al,
                                               const h16* Bh, const h16* Bl,
                                               uint32_t sbase)
{
    int k0 = j * BKE;
    uint32_t st = sbase + (j % NST) * STG;
#pragma unroll
    for (int t = 0; t < 4; t++) {
        int idx = tid + t * 256;
        int row = idx >> 3;
        int ch  = idx & 7;
        uint32_t off = SWZ((uint32_t)(row * 128 + ch * 16));
        size_t gA = (size_t)(m0 + row) * K + k0 + ch * 8;
        size_t gB = (size_t)(n0 + row) * K + k0 + ch * 8;
        CP_ASYNC16(st + G_AH + off, Ah + gA);
        CP_ASYNC16(st + G_AL + off, Al + gA);
        CP_ASYNC16(st + G_BH + off, Bh + gB);
        CP_ASYNC16(st + G_BL + off, Bl + gB);
    }
}

__global__ __launch_bounds__(256, 1) void gemm3(const h16* __restrict__ Ah,
                                                const h16* __restrict__ Al,
                                                const h16* __restrict__ Bh,
                                                const h16* __restrict__ Bl,
                                                float* __restrict__ C,
                                                int M, int N, int K)
{
    extern __shared__ char smem[];
    const uint32_t sbase = smem_u32(smem);
    const int tid  = threadIdx.x;
    const int lane = tid & 31;
    const int wid  = tid >> 5;
    const int wm   = wid & 3;
    const int wn   = wid >> 2;
    const int m0 = blockIdx.y * BM;
    const int n0 = blockIdx.x * BN;
    const int kchunks = K / BKE;

    float acc[2][8][4];
#pragma unroll
    for (int i = 0; i < 2; i++)
#pragma unroll
        for (int j = 0; j < 8; j++)
#pragma unroll
            for (int r = 0; r < 4; r++) acc[i][j][r] = 0.f;

    uint32_t arowr[2], browr[4];
#pragma unroll
    for (int i = 0; i < 2; i++)
        arowr[i] = (uint32_t)((wm * 32 + i * 16 + (lane & 15)) * 128 + (lane >> 4) * 16);
#pragma unroll
    for (int p = 0; p < 4; p++)
        browr[p] = (uint32_t)((wn * 64 + p * 16 + (lane & 7) + ((lane >> 4) << 3)) * 128 +
                              ((lane >> 3) & 1) * 16);

    for (int j = 0; j < 3 && j < kchunks; j++) {
        issue_loads_g3(j, tid, m0, n0, K, Ah, Al, Bh, Bl, sbase);
        CP_COMMIT();
    }

    for (int it = 0; it < kchunks; it++) {
        uint32_t st = sbase + (it % NST) * STG;
        CP_WAIT2();
        __syncthreads();

#pragma unroll
        for (int ks = 0; ks < 4; ks++) {
            uint32_t kb = ks * 32;
            uint32_t ah[2][4], al[2][4], bh[4][4], bl[4][4];
#pragma unroll
            for (int i = 0; i < 2; i++) {
                uint32_t off = SWZ(arowr[i] + kb);
                LDSM4(ah[i][0], ah[i][1], ah[i][2], ah[i][3], st + G_AH + off);
                LDSM4(al[i][0], al[i][1], al[i][2], al[i][3], st + G_AL + off);
            }
#pragma unroll
            for (int p = 0; p < 4; p++) {
                uint32_t off = SWZ(browr[p] + kb);
                LDSM4(bh[p][0], bh[p][1], bh[p][2], bh[p][3], st + G_BH + off);
                LDSM4(bl[p][0], bl[p][1], bl[p][2], bl[p][3], st + G_BL + off);
            }
#pragma unroll
            for (int i = 0; i < 2; i++)
#pragma unroll
                for (int j = 0; j < 8; j++) {
                    int p = j >> 1;
                    int h = (j & 1) << 1;
                    mma16816(acc[i][j], ah[i], bh[p][h], bh[p][h + 1]);
                    mma16816(acc[i][j], al[i], bh[p][h], bh[p][h + 1]);
                    mma16816(acc[i][j], ah[i], bl[p][h], bl[p][h + 1]);
                }
        }
        __syncthreads();

        int nj = it + 3;
        if (nj < kchunks)
            issue_loads_g3(nj, tid, m0, n0, K, Ah, Al, Bh, Bl, sbase);
        CP_COMMIT();
    }

    const int g   = lane >> 2;
    const int tig = lane & 3;
#pragma unroll
    for (int i = 0; i < 2; i++) {
        int row = m0 + wm * 32 + i * 16 + g;
#pragma unroll
        for (int j = 0; j < 8; j++) {
            int col = n0 + wn * 64 + j * 8 + 2 * tig;
            *(float2*)&C[(size_t)row * N + col] =
                make_float2(acc[i][j][0], acc[i][j][1]);
            *(float2*)&C[(size_t)(row + 8) * N + col] =
                make_float2(acc[i][j][2], acc[i][j][3]);
        }
    }
}

// ======================== gemm2: C = A*B^T, 2 products ======================
// A split (Ah,Al), B single fp16. acc += AhB + AlB (exact in A).
// out16: 0 -> fp32 C, 1 -> fp16 C.
#define G2_AH 0
#define G2_AL 16384
#define G2_B  32768
#define STG2  49152
#define NST2  4
#define GEMM2_SMEM (NST2 * STG2)

__device__ __forceinline__ void issue_loads_g2(int j, int tid, int m0, int n0, int K,
                                               const h16* Ah, const h16* Al,
                                               const h16* B, uint32_t sbase)
{
    int k0 = j * BKE;
    uint32_t st = sbase + (j % NST2) * STG2;
#pragma unroll
    for (int t = 0; t < 4; t++) {
        int idx = tid + t * 256;
        int row = idx >> 3;
        int ch  = idx & 7;
        uint32_t off = SWZ((uint32_t)(row * 128 + ch * 16));
        size_t gA = (size_t)(m0 + row) * K + k0 + ch * 8;
        size_t gB = (size_t)(n0 + row) * K + k0 + ch * 8;
        CP_ASYNC16(st + G2_AH + off, Ah + gA);
        CP_ASYNC16(st + G2_AL + off, Al + gA);
        CP_ASYNC16(st + G2_B  + off, B + gB);
    }
}

__global__ __launch_bounds__(256, 1) void gemm2(const h16* __restrict__ Ah,
                                                const h16* __restrict__ Al,
                                                const h16* __restrict__ B,
                                                void* __restrict__ Cout,
                                                int M, int N, int K, int out16)
{
    extern __shared__ char smem[];
    const uint32_t sbase = smem_u32(smem);
    const int tid  = threadIdx.x;
    const int lane = tid & 31;
    const int wid  = tid >> 5;
    const int wm   = wid & 3;
    const int wn   = wid >> 2;
    const int m0 = blockIdx.y * BM;
    const int n0 = blockIdx.x * BN;
    const int kchunks = K / BKE;

    float acc[2][8][4];
#pragma unroll
    for (int i = 0; i < 2; i++)
#pragma unroll
        for (int j = 0; j < 8; j++)
#pragma unroll
            for (int r = 0; r < 4; r++) acc[i][j][r] = 0.f;

    uint32_t arowr[2], browr[4];
#pragma unroll
    for (int i = 0; i < 2; i++)
        arowr[i] = (uint32_t)((wm * 32 + i * 16 + (lane & 15)) * 128 + (lane >> 4) * 16);
#pragma unroll
    for (int p = 0; p < 4; p++)
        browr[p] = (uint32_t)((wn * 64 + p * 16 + (lane & 7) + ((lane >> 4) << 3)) * 128 +
                              ((lane >> 3) & 1) * 16);

    for (int j = 0; j < 3 && j < kchunks; j++) {
        issue_loads_g2(j, tid, m0, n0, K, Ah, Al, B, sbase);
        CP_COMMIT();
    }

    for (int it = 0; it < kchunks; it++) {
        uint32_t st = sbase + (it % NST2) * STG2;
        CP_WAIT2();
        __syncthreads();
        // issue next stage BEFORE compute (4 buffers: no conflict with stage it)
        int nj = it + 3;
        if (nj < kchunks)
            issue_loads_g2(nj, tid, m0, n0, K, Ah, Al, B, sbase);
        CP_COMMIT();

#pragma unroll
        for (int ks = 0; ks < 4; ks++) {
            uint32_t kb = ks * 32;
            uint32_t ah[2][4], al[2][4], b[4][4];
#pragma unroll
            for (int i = 0; i < 2; i++) {
                uint32_t off = SWZ(arowr[i] + kb);
                LDSM4(ah[i][0], ah[i][1], ah[i][2], ah[i][3], st + G2_AH + off);
                LDSM4(al[i][0], al[i][1], al[i][2], al[i][3], st + G2_AL + off);
            }
#pragma unroll
            for (int p = 0; p < 4; p++) {
                uint32_t off = SWZ(browr[p] + kb);
                LDSM4(b[p][0], b[p][1], b[p][2], b[p][3], st + G2_B + off);
            }
#pragma unroll
            for (int i = 0; i < 2; i++)
#pragma unroll
                for (int j = 0; j < 8; j++) {
                    int p = j >> 1;
                    int h = (j & 1) << 1;
                    mma16816(acc[i][j], ah[i], b[p][h], b[p][h + 1]);
                    mma16816(acc[i][j], al[i], b[p][h], b[p][h + 1]);
                }
        }
    }

    const int g   = lane >> 2;
    const int tig = lane & 3;
    if (!out16) {
        float* C = (float*)Cout;
#pragma unroll
        for (int i = 0; i < 2; i++) {
            int row = m0 + wm * 32 + i * 16 + g;
#pragma unroll
            for (int j = 0; j < 8; j++) {
                int col = n0 + wn * 64 + j * 8 + 2 * tig;
                *(float2*)&C[(size_t)row * N + col] =
                    make_float2(acc[i][j][0], acc[i][j][1]);
                *(float2*)&C[(size_t)(row + 8) * N + col] =
                    make_float2(acc[i][j][2], acc[i][j][3]);
            }
        }
    } else {
        h16* C = (h16*)Cout;
#pragma unroll
        for (int i = 0; i < 2; i++) {
            int row = m0 + wm * 32 + i * 16 + g;
#pragma unroll
            for (int j = 0; j < 8; j++) {
                int col = n0 + wn * 64 + j * 8 + 2 * tig;
                *(uint32_t*)&C[(size_t)row * N + col] = pack_h2(acc[i][j][0], acc[i][j][1]);
                *(uint32_t*)&C[(size_t)(row + 8) * N + col] = pack_h2(acc[i][j][2], acc[i][j][3]);
            }
        }
    }
}

// ---------------------------------------------------------------------------
// Fused RoPE + fp16 hi/lo split. Reads fp32 g_Q/g_K, writes split fp16 arrays.
// ---------------------------------------------------------------------------
__global__ __launch_bounds__(64) void rope_split_kernel()
{
    const int s = blockIdx.x;
    const int h = blockIdx.y;
    const int i = threadIdx.x;   // 0..63

    const float* p;
    h16 *oh, *ol;
    if (h < NH) {
        size_t base = (size_t)s * HID + h * HD;
        p = &g_Q[base]; oh = &g_Qh[base]; ol = &g_Ql[base];
    } else {
        size_t base = (size_t)s * KVDIM + (h - NH) * HD;
        p = &g_K[base]; oh = &g_Kh[base]; ol = &g_Kl[base];
    }

    float freq = __powf(10000.0f, -((float)(2 * i)) / 128.0f);
    float ang  = (float)s * freq;
    float sn, c;
    sincosf(ang, &sn, &c);

    float x1 = p[i];
    float x2 = p[i + 64];
    float y1 = x1 * c - x2 * sn;
    float y2 = x2 * c + x1 * sn;

    h16 h1 = __float2half(y1);
    h16 h2 = __float2half(y2);
    oh[i]      = h1;
    oh[i + 64] = h2;
    ol[i]      = __float2half(y1 - __half2float(h1));
    ol[i + 64] = __float2half(y2 - __half2float(h2));
}

// ---------------------------------------------------------------------------
// HMMA flash attention: QK^T 3-product (Qh,Ql x Kh,Kl), PV 2-product
// (Ph,Pl x V single fp16). 2-stage KV cp.async pipeline. Writes A hi/lo fp16.
// ---------------------------------------------------------------------------
#define F_QH 0
#define F_QL 32768
#define F_KV 65536
#define KVSTG 49152       // {Kh 16K, Kl 16K, V 16K}
#define FLASH_SMEM (F_KV + 2 * KVSTG)   // 163840

__device__ __forceinline__ void flash_issue_kv(int jt, int tid, int kvh, uint32_t sbase)
{
    uint32_t st = sbase + F_KV + (jt & 1) * KVSTG;
#pragma unroll
    for (int t = 0; t < 12; t++) {
        int idx = tid + t * 256;              // 0..3071
        int tile = idx >> 10;                 // 0:Kh 1:Kl 2:V
        int r    = (idx >> 4) & 63;
        int ch   = idx & 15;
        uint32_t off = SWZV((uint32_t)(r * 256 + ch * 16));
        size_t gsrc = (size_t)(jt * 64 + r) * KVDIM + kvh * HD + ch * 8;
        const h16* base = (tile == 0) ? g_Kh : (tile == 1) ? g_Kl : g_V16;
        CP_ASYNC16(st + tile * 16384 + off, base + gsrc);
    }
}

__global__ __launch_bounds__(256, 1) void flash_mma()
{
    extern __shared__ char smem[];
    const uint32_t sbase = smem_u32(smem);
    const int tid  = threadIdx.x;
    const int lane = tid & 31;
    const int wid  = tid >> 5;
    const int qt   = blockIdx.x;
    const int h    = blockIdx.y;
    const int kvh  = h >> 2;
    const int q0   = qt * 128;
    const int g    = lane >> 2;
    const int tig  = lane & 3;

    // Q hi/lo: 128 rows x 256B, SWZV
#pragma unroll
    for (int t = 0; t < 16; t++) {
        int idx = tid + t * 256;
        int tile = idx >> 11;
        int r    = (idx >> 4) & 127;
        int ch   = idx & 15;
        uint32_t off = SWZV((uint32_t)(r * 256 + ch * 16));
        const h16* src = (tile ? g_Ql : g_Qh) + (size_t)(q0 + r) * HID + h * HD + ch * 8;
        CP_ASYNC16(sbase + (tile ? F_QL : F_QH) + off, src);
    }
    CP_COMMIT();

    const int ntiles = 2 * qt + 2;
    flash_issue_kv(0, tid, kvh, sbase);
    CP_COMMIT();
    flash_issue_kv(1, tid, kvh, sbase);
    CP_COMMIT();

    float of[16][4];
#pragma unroll
    for (int nt = 0; nt < 16; nt++)
#pragma unroll
        for (int r = 0; r < 4; r++) of[nt][r] = 0.f;
    float m0 = -INFINITY, m1 = -INFINITY, l0 = 0.f, l1 = 0.f;

    const float scale = 0.08838834764831845f;
    const int rg0 = q0 + wid * 16 + g;
    const int rg1 = rg0 + 8;

    uint32_t aoffQ = (uint32_t)((wid * 16 + (lane & 15)) * 256 + (lane >> 4) * 16);
    uint32_t boffK[4];
#pragma unroll
    for (int p = 0; p < 4; p++)
        boffK[p] = (uint32_t)((p * 16 + (lane & 7) + ((lane >> 4) << 3)) * 256 +
                              ((lane >> 3) & 1) * 16);
    uint32_t voffr = (uint32_t)(((lane & 7) + ((lane >> 3) & 1) * 8) * 256 +
                                (lane >> 4) * 16);

    for (int jt = 0; jt < ntiles; jt++) {
        uint32_t st = sbase + F_KV + (jt & 1) * KVSTG;
        CP_WAIT1();            // Q + kv(jt) resident; kv(jt+1) may pend
        __syncthreads();

        // --- S = Qh*Kh^T + Ql*Kh^T + Qh*Kl^T ---
        float sfrag[8][4];
#pragma unroll
        for (int j = 0; j < 8; j++)
#pragma unroll
            for (int r = 0; r < 4; r++) sfrag[j][r] = 0.f;

#pragma unroll
        for (int ks = 0; ks < 8; ks++) {
            uint32_t kb = ks * 32;
            uint32_t qh[4], ql[4], kh[4][4], kl[4][4];
            uint32_t qo = SWZV(aoffQ + kb);
            LDSM4(qh[0], qh[1], qh[2], qh[3], sbase + F_QH + qo);
            LDSM4(ql[0], ql[1], ql[2], ql[3], sbase + F_QL + qo);
#pragma unroll
            for (int p = 0; p < 4; p++) {
                uint32_t ko = SWZV(boffK[p] + kb);
                LDSM4(kh[p][0], kh[p][1], kh[p][2], kh[p][3], st + 0 + ko);
                LDSM4(kl[p][0], kl[p][1], kl[p][2], kl[p][3], st + 16384 + ko);
            }
#pragma unroll
            for (int j = 0; j < 8; j++) {
                int p = j >> 1;
                int hs = (j & 1) << 1;
                mma16816(sfrag[j], qh, kh[p][hs], kh[p][hs + 1]);
                mma16816(sfrag[j], ql, kh[p][hs], kh[p][hs + 1]);
                mma16816(sfrag[j], qh, kl[p][hs], kl[p][hs + 1]);
            }
        }

        // --- scale + causal mask ---
#pragma unroll
        for (int j = 0; j < 8; j++) {
            int cg = jt * 64 + j * 8 + 2 * tig;
            float c0 = sfrag[j][0] * scale; if (cg     > rg0) c0 = -INFINITY;
            float c1 = sfrag[j][1] * scale; if (cg + 1 > rg0) c1 = -INFINITY;
            float c2 = sfrag[j][2] * scale; if (cg     > rg1) c2 = -INFINITY;
            float c3 = sfrag[j][3] * scale; if (cg + 1 > rg1) c3 = -INFINITY;
            sfrag[j][0] = c0; sfrag[j][1] = c1; sfrag[j][2] = c2; sfrag[j][3] = c3;
        }

        // --- online softmax (rows g, g+8) ---
        float mx0 = -INFINITY, mx1 = -INFINITY;
#pragma unroll
        for (int j = 0; j < 8; j++) {
            mx0 = fmaxf(mx0, fmaxf(sfrag[j][0], sfrag[j][1]));
            mx1 = fmaxf(mx1, fmaxf(sfrag[j][2], sfrag[j][3]));
        }
        mx0 = fmaxf(mx0, __shfl_xor_sync(0xffffffffu, mx0, 1));
        mx0 = fmaxf(mx0, __shfl_xor_sync(0xffffffffu, mx0, 2));
        mx1 = fmaxf(mx1, __shfl_xor_sync(0xffffffffu, mx1, 1));
        mx1 = fmaxf(mx1, __shfl_xor_sync(0xffffffffu, mx1, 2));
        float mn0 = fmaxf(m0, mx0);
        float mn1 = fmaxf(m1, mx1);
        float f0 = __expf(m0 - mn0);
        float f1 = __expf(m1 - mn1);

        uint32_t ph0[8], ph1[8], pl0[8], pl1[8];
        float s0 = 0.f, s1 = 0.f;
#pragma unroll
        for (int j = 0; j < 8; j++) {
            float e0 = __expf(sfrag[j][0] - mn0);
            float e1 = __expf(sfrag[j][1] - mn0);
            float e2 = __expf(sfrag[j][2] - mn1);
            float e3 = __expf(sfrag[j][3] - mn1);
            s0 += e0 + e1; s1 += e2 + e3;
            h16 a0 = __float2half(e0), a1 = __float2half(e1);
            h16 a2 = __float2half(e2), a3 = __float2half(e3);
            ph0[j] = pack_h2(e0, e1);
            ph1[j] = pack_h2(e2, e3);
            pl0[j] = pack_h2(e0 - __half2float(a0), e1 - __half2float(a1));
            pl1[j] = pack_h2(e2 - __half2float(a2), e3 - __half2float(a3));
        }
        s0 += __shfl_xor_sync(0xffffffffu, s0, 1);
        s0 += __shfl_xor_sync(0xffffffffu, s0, 2);
        s1 += __shfl_xor_sync(0xffffffffu, s1, 1);
        s1 += __shfl_xor_sync(0xffffffffu, s1, 2);
        l0 = l0 * f0 + s0;
        l1 = l1 * f1 + s1;
        m0 = mn0; m1 = mn1;
#pragma unroll
        for (int nt = 0; nt < 16; nt++) {
            of[nt][0] *= f0; of[nt][1] *= f0;
            of[nt][2] *= f1; of[nt][3] *= f1;
        }

        // --- O += Ph*V + Pl*V  (V single fp16, ldmatrix.trans) ---
#pragma unroll
        for (int kk = 0; kk < 4; kk++) {
            uint32_t ah[4] = {ph0[2 * kk], ph1[2 * kk], ph0[2 * kk + 1], ph1[2 * kk + 1]};
            uint32_t al[4] = {pl0[2 * kk], pl1[2 * kk], pl0[2 * kk + 1], pl1[2 * kk + 1]};
#pragma unroll
            for (int np = 0; np < 8; np++) {
                uint32_t off = SWZV((uint32_t)(kk * 16 * 256) + voffr + (uint32_t)(np * 32));
                uint32_t v0, v1, v2, v3;
                LDSM4T(v0, v1, v2, v3, st + 32768 + off);
                mma16816(of[2 * np],     ah, v0, v1);
                mma16816(of[2 * np + 1], ah, v2, v3);
                mma16816(of[2 * np],     al, v0, v1);
                mma16816(of[2 * np + 1], al, v2, v3);
            }
        }
        __syncthreads();

        // issue kv(jt+2) into stage (jt&1) — safe after sync
        int nj = jt + 2;
        if (nj < ntiles)
            flash_issue_kv(nj, tid, kvh, sbase);
        CP_COMMIT();
    }

    // --- normalize + split-store to Ah/Al ---
    float inv0 = 1.f / l0;
    float inv1 = 1.f / l1;
#pragma unroll
    for (int nt = 0; nt < 16; nt++) {
        int col = h * HD + nt * 8 + 2 * tig;
        float v00 = of[nt][0] * inv0, v01 = of[nt][1] * inv0;
        float v10 = of[nt][2] * inv1, v11 = of[nt][3] * inv1;
        h16 h00 = __float2half(v00), h01 = __float2half(v01);
        h16 h10 = __float2half(v10), h11 = __float2half(v11);
        *(uint32_t*)&g_Ah[(size_t)rg0 * HID + col] = pack_h2(v00, v01);
        *(uint32_t*)&g_Al[(size_t)rg0 * HID + col] =
            pack_h2(v00 - __half2float(h00), v01 - __half2float(h01));
        *(uint32_t*)&g_Ah[(size_t)rg1 * HID + col] = pack_h2(v10, v11);
        *(uint32_t*)&g_Al[(size_t)rg1 * HID + col] =
            pack_h2(v10 - __half2float(h10), v11 - __half2float(h11));
    }
}

// ---------------------------------------------------------------------------
extern "C" void kernel_launch(void* const* d_in, const int* in_sizes, int n_in,
                              void* d_out, int out_size)
{
    const float* X  = (const float*)d_in[0];
    const float* Wq = (const float*)d_in[1];
    const float* Wk = (const float*)d_in[2];
    const float* Wv = (const float*)d_in[3];
    const float* Wo = (const float*)d_in[4];
    float* out = (float*)d_out;

    float *Qp, *Kp;
    cudaGetSymbolAddress((void**)&Qp, g_Q);
    cudaGetSymbolAddress((void**)&Kp, g_K);
    h16 *Xh, *Xl, *Wqh, *Wql, *Wkh, *Wkl, *Wv16, *Wo16, *V16, *Ahp, *Alp;
    cudaGetSymbolAddress((void**)&Xh,   g_Xh);   cudaGetSymbolAddress((void**)&Xl,  g_Xl);
    cudaGetSymbolAddress((void**)&Wqh,  g_Wqh);  cudaGetSymbolAddress((void**)&Wql, g_Wql);
    cudaGetSymbolAddress((void**)&Wkh,  g_Wkh);  cudaGetSymbolAddress((void**)&Wkl, g_Wkl);
    cudaGetSymbolAddress((void**)&Wv16, g_Wv16); cudaGetSymbolAddress((void**)&Wo16, g_Wo16);
    cudaGetSymbolAddress((void**)&V16,  g_V16);
    cudaGetSymbolAddress((void**)&Ahp,  g_Ah);   cudaGetSymbolAddress((void**)&Alp, g_Al);

    cudaFuncSetAttribute(gemm3, cudaFuncAttributeMaxDynamicSharedMemorySize, GEMM3_SMEM);
    cudaFuncSetAttribute(gemm2, cudaFuncAttributeMaxDynamicSharedMemorySize, GEMM2_SMEM);
    cudaFuncSetAttribute(flash_mma, cudaFuncAttributeMaxDynamicSharedMemorySize, FLASH_SMEM);

    const int nX  = S_LEN * HID / 4;
    const int nWq = HID * HID / 4;
    const int nWk = KVDIM * HID / 4;

    // splits / converts
    split16_kernel<<<nX / 256, 256>>>((const float4*)X, (__half2*)Xh, (__half2*)Xl, nX);
    split16_kernel<<<nWq / 256, 256>>>((const float4*)Wq, (__half2*)Wqh, (__half2*)Wql, nWq);
    split16_kernel<<<nWk / 256, 256>>>((const float4*)Wk, (__half2*)Wkh, (__half2*)Wkl, nWk);
    conv16_kernel<<<nWk / 256, 256>>>((const float4*)Wv, (__half2*)Wv16, nWk);
    conv16_kernel<<<nWq / 256, 256>>>((const float4*)Wo, (__half2*)Wo16, nWq);

    // projections: Q/K 3-product (score path), V 2-product fp16-out
    gemm3<<<dim3(HID / BN, S_LEN / BM), 256, GEMM3_SMEM>>>(Xh, Xl, Wqh, Wql, Qp, S_LEN, HID, HID);
    gemm3<<<dim3(KVDIM / BN, S_LEN / BM), 256, GEMM3_SMEM>>>(Xh, Xl, Wkh, Wkl, Kp, S_LEN, KVDIM, HID);
    gemm2<<<dim3(KVDIM / BN, S_LEN / BM), 256, GEMM2_SMEM>>>(Xh, Xl, Wv16, V16, S_LEN, KVDIM, HID, 1);

    // fused rope + split
    rope_split_kernel<<<dim3(S_LEN, NH + NKV), 64>>>();

    // attention (writes Ah/Al)
    flash_mma<<<dim3(S_LEN / 128, NH), 256, FLASH_SMEM>>>();

    // O projection: 2-product, fp32 out
    gemm2<<<dim3(HID / BN, S_LEN / BM), 256, GEMM2_SMEM>>>(Ahp, Alp, Wo16, out, S_LEN, HID, HID, 0);
}